// round 4
// baseline (speedup 1.0000x reference)
#include <cuda_runtime.h>

#define NMAX 100000
#define EMAX 1600000
#define HDIM 128

// Scratch (static device globals — no runtime allocation). 16B-aligned so
// float4 (128-bit) accesses are legal.
__device__ __align__(16) int   g_is64;                       // edge dtype flag
__device__ __align__(16) int   g_esrc[EMAX];                 // decoded src
__device__ __align__(16) int   g_edst[EMAX];                 // decoded dst
__device__ __align__(16) int   g_cnt [NMAX];                 // incoming-edge count
__device__ __align__(16) int   g_off [NMAX];                 // CSR offsets
__device__ __align__(16) int   g_cur [NMAX];                 // bucket cursors
__device__ __align__(16) float g_dinv[NMAX];                 // 1/sqrt(deg)
__device__ __align__(16) int   g_src [EMAX];                 // dst-sorted sources
__device__ __align__(16) float g_nrm [EMAX];                 // dst-sorted norms
__device__ __align__(16) float g_h   [(size_t)NMAX * HDIM];  // x @ W_conv
__device__ __align__(16) float g_hs  [(size_t)NMAX * HDIM];  // x @ W_skip

// ---------------------------------------------------------------- dtype detect
// If data is int64 (little-endian), every odd int32 word of the first 64
// entries is the high half of a value < 2^32, i.e. 0. If data is int32,
// those words are random node indices (all-zero is impossible in practice).
__global__ void k_detect(const int* __restrict__ ei32) {
    if (blockIdx.x == 0 && threadIdx.x == 0) {
        int ornz = 0;
        for (int i = 0; i < 64; i++) ornz |= ei32[2 * i + 1];
        g_is64 = (ornz == 0) ? 1 : 0;
    }
}

// ---------------------------------------------------------------- decode + clamp
__global__ void k_convert(const void* __restrict__ ei, int E, int n) {
    int e = blockIdx.x * blockDim.x + threadIdx.x;
    if (e >= E) return;
    int src, dst;
    if (g_is64) {
        src = (int)((const long long*)ei)[e];
        dst = (int)((const long long*)ei)[(size_t)E + e];
    } else {
        src = ((const int*)ei)[e];
        dst = ((const int*)ei)[(size_t)E + e];
    }
    // safety clamp (indices are expected in [0, n) already)
    src = min(max(src, 0), n - 1);
    dst = min(max(dst, 0), n - 1);
    g_esrc[e] = src;
    g_edst[e] = dst;
}

// ---------------------------------------------------------------- init
__global__ void k_init(int n) {
    int i = blockIdx.x * blockDim.x + threadIdx.x;
    if (i < n) { g_cnt[i] = 0; g_cur[i] = 0; }
}

// ---------------------------------------------------------------- degree histogram
__global__ void k_deg(int E) {
    int e = blockIdx.x * blockDim.x + threadIdx.x;
    if (e < E) atomicAdd(&g_cnt[g_edst[e]], 1);
}

__global__ void k_dinv(int n) {
    int i = blockIdx.x * blockDim.x + threadIdx.x;
    if (i < n) g_dinv[i] = rsqrtf((float)g_cnt[i] + 2.0f);  // improved=True: +2 self-loop
}

// ---------------------------------------------------------------- exclusive scan (1 block)
__global__ void k_scan(int n) {
    __shared__ int ssum[1024];
    const int tid = threadIdx.x;
    const int per = (n + 1023) / 1024;
    const int beg = tid * per;
    const int end = min(beg + per, n);

    int s = 0;
    for (int i = beg; i < end; i++) s += g_cnt[i];
    ssum[tid] = s;
    __syncthreads();

    int own = s;
    for (int off = 1; off < 1024; off <<= 1) {
        int t = (tid >= off) ? ssum[tid - off] : 0;
        __syncthreads();
        ssum[tid] += t;
        __syncthreads();
    }
    int run = ssum[tid] - own;   // exclusive base for this chunk

    for (int i = beg; i < end; i++) {
        g_off[i] = run;
        run += g_cnt[i];
    }
}

// ---------------------------------------------------------------- bucket (counting sort by dst)
__global__ void k_bucket(int E) {
    int e = blockIdx.x * blockDim.x + threadIdx.x;
    if (e >= E) return;
    int src = g_esrc[e];
    int dst = g_edst[e];
    int pos = g_off[dst] + atomicAdd(&g_cur[dst], 1);
    g_src[pos] = src;
    g_nrm[pos] = g_dinv[src] * g_dinv[dst];
}

// ---------------------------------------------------------------- fused dual GEMM
// Per block: 16 nodes x 256 output cols (128 conv | 128 skip), K chunked by 32.
// Static shared only (~35 KB), thread tile 4 nodes x 4 cols.
#define SX_PITCH 20   // 16 nodes + pad (80B rows, float4-aligned)

__global__ void k_gemm(const float* __restrict__ x,
                       const float* __restrict__ Wc,
                       const float* __restrict__ Ws, int n) {
    __shared__ __align__(16) float sW[32 * 256];       // K-chunk of [W_conv|W_skip]
    __shared__ __align__(16) float sx[32 * SX_PITCH];  // K-chunk of x tile, k-major

    const int tid   = threadIdx.x;
    const int node0 = blockIdx.x * 16;
    const int c = tid & 63;    // col group: cols 4c..4c+3 of 256
    const int r = tid >> 6;    // node group: nodes 4r..4r+3 of 16

    float4 acc[4];
    acc[0] = acc[1] = acc[2] = acc[3] = make_float4(0.f, 0.f, 0.f, 0.f);

    for (int kc = 0; kc < 4; kc++) {
        // W rows [kc*32, kc*32+32): 32 rows x 64 float4
        for (int f = tid; f < 32 * 64; f += 256) {
            int k    = f >> 6;
            int j4   = f & 63;
            int krow = kc * 32 + k;
            float4 v = (j4 < 32) ? ((const float4*)Wc)[krow * 32 + j4]
                                 : ((const float4*)Ws)[krow * 32 + (j4 - 32)];
            ((float4*)&sW[k * 256])[j4] = v;
        }
        // x tile: 16 nodes x 8 float4 of this K chunk, stored transposed
        if (tid < 128) {
            int nloc = tid & 15;
            int k4   = tid >> 4;               // 0..7
            int node = node0 + nloc;
            float4 v = make_float4(0.f, 0.f, 0.f, 0.f);
            if (node < n) v = ((const float4*)x)[(size_t)node * 32 + kc * 8 + k4];
            sx[(k4 * 4 + 0) * SX_PITCH + nloc] = v.x;
            sx[(k4 * 4 + 1) * SX_PITCH + nloc] = v.y;
            sx[(k4 * 4 + 2) * SX_PITCH + nloc] = v.z;
            sx[(k4 * 4 + 3) * SX_PITCH + nloc] = v.w;
        }
        __syncthreads();

#pragma unroll
        for (int k = 0; k < 32; k++) {
            float4 wv = *(const float4*)&sW[k * 256 + c * 4];
            float4 xv = *(const float4*)&sx[k * SX_PITCH + r * 4];
            acc[0].x += xv.x * wv.x; acc[0].y += xv.x * wv.y;
            acc[0].z += xv.x * wv.z; acc[0].w += xv.x * wv.w;
            acc[1].x += xv.y * wv.x; acc[1].y += xv.y * wv.y;
            acc[1].z += xv.y * wv.z; acc[1].w += xv.y * wv.w;
            acc[2].x += xv.z * wv.x; acc[2].y += xv.z * wv.y;
            acc[2].z += xv.z * wv.z; acc[2].w += xv.z * wv.w;
            acc[3].x += xv.w * wv.x; acc[3].y += xv.w * wv.y;
            acc[3].z += xv.w * wv.z; acc[3].w += xv.w * wv.w;
        }
        __syncthreads();
    }

#pragma unroll
    for (int i = 0; i < 4; i++) {
        int node = node0 + r * 4 + i;
        if (node < n) {
            if (c < 32) ((float4*)&g_h [(size_t)node * HDIM])[c]      = acc[i];
            else        ((float4*)&g_hs[(size_t)node * HDIM])[c - 32] = acc[i];
        }
    }
}

// ---------------------------------------------------------------- fused aggregation + epilogue
// One warp per node. Lane l owns features [4l, 4l+4). Atomic-free.
__global__ void k_agg(const float* __restrict__ bconv,
                      const float* __restrict__ bskip,
                      float* __restrict__ out, int n) {
    int node = (blockIdx.x * blockDim.x + threadIdx.x) >> 5;
    int lane = threadIdx.x & 31;
    if (node >= n) return;

    const int beg = g_off[node];
    const int end = beg + g_cnt[node];

    float4 acc = make_float4(0.f, 0.f, 0.f, 0.f);
    for (int j = beg; j < end; j++) {
        int   src  = g_src[j];     // uniform across warp
        float norm = g_nrm[j];     // uniform across warp
        float4 hv = ((const float4*)&g_h[(size_t)src * HDIM])[lane];
        acc.x += norm * hv.x;
        acc.y += norm * hv.y;
        acc.z += norm * hv.z;
        acc.w += norm * hv.w;
    }

    float di = g_dinv[node];
    float sw = 2.0f * di * di;     // self-loop weight * dinv^2

    float4 h4  = ((const float4*)&g_h [(size_t)node * HDIM])[lane];
    float4 hs4 = ((const float4*)&g_hs[(size_t)node * HDIM])[lane];
    float4 bc  = ((const float4*)bconv)[lane];
    float4 bs  = ((const float4*)bskip)[lane];

    float4 o;
    o.x = acc.x + sw * h4.x + bc.x + hs4.x + bs.x;
    o.y = acc.y + sw * h4.y + bc.y + hs4.y + bs.y;
    o.z = acc.z + sw * h4.z + bc.z + hs4.z + bs.z;
    o.w = acc.w + sw * h4.w + bc.w + hs4.w + bs.w;

    o.x = (o.x > 0.f) ? o.x : 0.1f * (expf(o.x) - 1.0f);
    o.y = (o.y > 0.f) ? o.y : 0.1f * (expf(o.y) - 1.0f);
    o.z = (o.z > 0.f) ? o.z : 0.1f * (expf(o.z) - 1.0f);
    o.w = (o.w > 0.f) ? o.w : 0.1f * (expf(o.w) - 1.0f);

    ((float4*)&out[(size_t)node * HDIM])[lane] = o;
}

// ---------------------------------------------------------------- launch
extern "C" void kernel_launch(void* const* d_in, const int* in_sizes, int n_in,
                              void* d_out, int out_size) {
    const float* x  = (const float*)d_in[0];
    const void*  ei = d_in[1];
    const float* Wc = (const float*)d_in[2];
    const float* bc = (const float*)d_in[3];
    const float* Ws = (const float*)d_in[4];
    const float* bs = (const float*)d_in[5];
    float* out = (float*)d_out;

    const int n = in_sizes[0] / HDIM;
    const int E = in_sizes[1] / 2;

    k_detect <<<1, 32>>>((const int*)ei);
    k_convert<<<(E + 255) / 256, 256>>>(ei, E, n);
    k_init   <<<(n + 255) / 256, 256>>>(n);
    k_deg    <<<(E + 255) / 256, 256>>>(E);
    k_dinv   <<<(n + 255) / 256, 256>>>(n);
    k_scan   <<<1, 1024>>>(n);
    k_bucket <<<(E + 255) / 256, 256>>>(E);

    k_gemm<<<(n + 15) / 16, 256>>>(x, Wc, Ws, n);

    long long athreads = (long long)n * 32;
    k_agg<<<(unsigned)((athreads + 255) / 256), 256>>>(bc, bs, out, n);
}

// round 5
// speedup vs baseline: 1.4332x; 1.4332x over previous
#include <cuda_runtime.h>

#define NMAX 100000
#define EMAX 1600000
#define HDIM 128

// Scratch (static device globals — no runtime allocation)
__device__ __align__(16) int    g_is64;                        // edge dtype flag
__device__             int      g_total;                       // bucket cursor base
__device__ __align__(16) int    g_cnt [NMAX];                  // incoming-edge count
__device__ __align__(16) int    g_off [NMAX];                  // bucket offsets
__device__ __align__(16) int    g_cur [NMAX];                  // bucket cursors
__device__ __align__(16) float  g_dinv[NMAX];                  // 1/sqrt(deg)
__device__ __align__(16) float2 g_edge[EMAX];                  // {src bits, norm} dst-bucketed
__device__ __align__(16) float  g_h   [(size_t)NMAX * HDIM];   // x @ W_conv
__device__ __align__(16) float  g_hs  [(size_t)NMAX * HDIM];   // x @ W_skip

union F2U { unsigned long long u; float2 f; };

__device__ __forceinline__ unsigned long long fma_f32x2(unsigned long long a,
                                                        unsigned long long b,
                                                        unsigned long long c) {
    unsigned long long d;
    asm("fma.rn.f32x2 %0, %1, %2, %3;" : "=l"(d) : "l"(a), "l"(b), "l"(c));
    return d;
}

__device__ __forceinline__ void decode_edge(const void* __restrict__ ei, int E,
                                            int n, int e, int& src, int& dst) {
    if (g_is64) {
        src = (int)((const long long*)ei)[e];
        dst = (int)((const long long*)ei)[(size_t)E + e];
    } else {
        src = ((const int*)ei)[e];
        dst = ((const int*)ei)[(size_t)E + e];
    }
    src = min(max(src, 0), n - 1);
    dst = min(max(dst, 0), n - 1);
}

// ---------------------------------------------------------------- dtype detect
// int64 little-endian indices < 2^32 have all-zero high words.
__global__ void k_detect(const int* __restrict__ ei32) {
    if (blockIdx.x == 0 && threadIdx.x == 0) {
        int ornz = 0;
        for (int i = 0; i < 64; i++) ornz |= ei32[2 * i + 1];
        g_is64 = (ornz == 0) ? 1 : 0;
    }
}

// ---------------------------------------------------------------- init
__global__ void k_init(int n) {
    int i = blockIdx.x * blockDim.x + threadIdx.x;
    if (i == 0) g_total = 0;
    if (i < n) g_cnt[i] = 0;
}

// ---------------------------------------------------------------- decode + degree histogram
__global__ void k_degree(const void* __restrict__ ei, int E, int n) {
    int e = blockIdx.x * blockDim.x + threadIdx.x;
    if (e >= E) return;
    int src, dst;
    decode_edge(ei, E, n, e, src, dst);
    atomicAdd(&g_cnt[dst], 1);
}

// ---------------------------------------------------------------- offsets (scan-free) + dinv
// Bucket placement order is irrelevant for a counting sort, so offsets come
// from a per-block scan + one global atomicAdd per block (no grid-wide scan).
__global__ void k_offsets(int n) {
    __shared__ int wsum[8];
    __shared__ int bbase;
    int i    = blockIdx.x * 256 + threadIdx.x;
    int lane = threadIdx.x & 31;
    int wid  = threadIdx.x >> 5;

    int c = (i < n) ? g_cnt[i] : 0;
    int v = c;
#pragma unroll
    for (int o = 1; o < 32; o <<= 1) {
        int t = __shfl_up_sync(0xffffffffu, v, o);
        if (lane >= o) v += t;
    }
    if (lane == 31) wsum[wid] = v;
    __syncthreads();
    if (threadIdx.x == 0) {
        int run = 0;
#pragma unroll
        for (int w = 0; w < 8; w++) { int t = wsum[w]; wsum[w] = run; run += t; }
        bbase = atomicAdd(&g_total, run);
    }
    __syncthreads();
    if (i < n) {
        int excl = bbase + wsum[wid] + v - c;
        g_off[i] = excl;
        g_cur[i] = excl;
        g_dinv[i] = rsqrtf((float)c + 2.0f);   // improved=True: +2 self-loop
    }
}

// ---------------------------------------------------------------- bucket (counting sort by dst)
__global__ void k_bucket(const void* __restrict__ ei, int E, int n) {
    int e = blockIdx.x * blockDim.x + threadIdx.x;
    if (e >= E) return;
    int src, dst;
    decode_edge(ei, E, n, e, src, dst);
    float nrm = g_dinv[src] * g_dinv[dst];
    int pos = atomicAdd(&g_cur[dst], 1);
    g_edge[pos] = make_float2(__int_as_float(src), nrm);
}

// ---------------------------------------------------------------- fused dual GEMM (packed f32x2)
// 32 nodes x 256 cols per block, 256 threads, thread tile 8 nodes x 4 cols.
// x stored DUPLICATED in smem ({x,x} per node) so the inner loop is pure
// FFMA2 + LDS: col-pairs come from the W float4, node-dups from sx2.
__global__ __launch_bounds__(256) void k_gemm(const float* __restrict__ x,
                                              const float* __restrict__ Wc,
                                              const float* __restrict__ Ws, int n) {
    __shared__ __align__(16) float sW [32 * 256];   // K-chunk of [W_conv|W_skip]
    __shared__ __align__(16) float sx2[32 * 64];    // K-chunk of x, duplicated pairs

    const int tid   = threadIdx.x;
    const int node0 = blockIdx.x * 32;
    const int c = tid & 63;    // cols 4c..4c+3
    const int r = tid >> 6;    // nodes r*8..r*8+7

    unsigned long long acc[8][2];
#pragma unroll
    for (int i = 0; i < 8; i++) { acc[i][0] = 0ull; acc[i][1] = 0ull; }

    for (int kc = 0; kc < 4; kc++) {
        // W rows [kc*32, kc*32+32): 32 rows x 64 float4
        for (int f = tid; f < 32 * 64; f += 256) {
            int k    = f >> 6;
            int j4   = f & 63;
            int krow = kc * 32 + k;
            float4 v = (j4 < 32) ? ((const float4*)Wc)[krow * 32 + j4]
                                 : ((const float4*)Ws)[krow * 32 + (j4 - 32)];
            ((float4*)&sW[k * 256])[j4] = v;
        }
        // x chunk: 32 nodes x 32 k, stored k-major with each value duplicated
        {
            int nloc = tid & 31;
            int k4   = tid >> 5;               // 0..7 (float4 along K)
            int node = node0 + nloc;
            float4 v = make_float4(0.f, 0.f, 0.f, 0.f);
            if (node < n) v = ((const float4*)x)[(size_t)node * 32 + kc * 8 + k4];
            ((float2*)&sx2[(k4 * 4 + 0) * 64])[nloc] = make_float2(v.x, v.x);
            ((float2*)&sx2[(k4 * 4 + 1) * 64])[nloc] = make_float2(v.y, v.y);
            ((float2*)&sx2[(k4 * 4 + 2) * 64])[nloc] = make_float2(v.z, v.z);
            ((float2*)&sx2[(k4 * 4 + 3) * 64])[nloc] = make_float2(v.w, v.w);
        }
        __syncthreads();

#pragma unroll 8
        for (int k = 0; k < 32; k++) {
            ulonglong2 wu = *(const ulonglong2*)&sW[k * 256 + c * 4];  // 2 col-pairs
            const ulonglong2* xp = (const ulonglong2*)&sx2[k * 64 + r * 16];
            ulonglong2 x01 = xp[0], x23 = xp[1], x45 = xp[2], x67 = xp[3];
            acc[0][0] = fma_f32x2(x01.x, wu.x, acc[0][0]);
            acc[0][1] = fma_f32x2(x01.x, wu.y, acc[0][1]);
            acc[1][0] = fma_f32x2(x01.y, wu.x, acc[1][0]);
            acc[1][1] = fma_f32x2(x01.y, wu.y, acc[1][1]);
            acc[2][0] = fma_f32x2(x23.x, wu.x, acc[2][0]);
            acc[2][1] = fma_f32x2(x23.x, wu.y, acc[2][1]);
            acc[3][0] = fma_f32x2(x23.y, wu.x, acc[3][0]);
            acc[3][1] = fma_f32x2(x23.y, wu.y, acc[3][1]);
            acc[4][0] = fma_f32x2(x45.x, wu.x, acc[4][0]);
            acc[4][1] = fma_f32x2(x45.x, wu.y, acc[4][1]);
            acc[5][0] = fma_f32x2(x45.y, wu.x, acc[5][0]);
            acc[5][1] = fma_f32x2(x45.y, wu.y, acc[5][1]);
            acc[6][0] = fma_f32x2(x67.x, wu.x, acc[6][0]);
            acc[6][1] = fma_f32x2(x67.x, wu.y, acc[6][1]);
            acc[7][0] = fma_f32x2(x67.y, wu.x, acc[7][0]);
            acc[7][1] = fma_f32x2(x67.y, wu.y, acc[7][1]);
        }
        __syncthreads();
    }

#pragma unroll
    for (int i = 0; i < 8; i++) {
        int node = node0 + r * 8 + i;
        if (node < n) {
            F2U a0, a1;
            a0.u = acc[i][0];
            a1.u = acc[i][1];
            float4 o = make_float4(a0.f.x, a0.f.y, a1.f.x, a1.f.y);
            if (c < 32) ((float4*)&g_h [(size_t)node * HDIM])[c]      = o;
            else        ((float4*)&g_hs[(size_t)node * HDIM])[c - 32] = o;
        }
    }
}

// ---------------------------------------------------------------- fused aggregation + epilogue
// One warp per node, lane l owns features [4l, 4l+4). Unroll-4 for MLP.
__global__ __launch_bounds__(256) void k_agg(const float* __restrict__ bconv,
                                             const float* __restrict__ bskip,
                                             float* __restrict__ out, int n) {
    int node = (blockIdx.x * blockDim.x + threadIdx.x) >> 5;
    int lane = threadIdx.x & 31;
    if (node >= n) return;

    const int beg = g_off[node];
    const int end = beg + g_cnt[node];

    float4 acc = make_float4(0.f, 0.f, 0.f, 0.f);
    int j = beg;
    for (; j + 4 <= end; j += 4) {
        float2 e0 = g_edge[j + 0];
        float2 e1 = g_edge[j + 1];
        float2 e2 = g_edge[j + 2];
        float2 e3 = g_edge[j + 3];
        float4 h0 = ((const float4*)&g_h[(size_t)__float_as_int(e0.x) * HDIM])[lane];
        float4 h1 = ((const float4*)&g_h[(size_t)__float_as_int(e1.x) * HDIM])[lane];
        float4 h2 = ((const float4*)&g_h[(size_t)__float_as_int(e2.x) * HDIM])[lane];
        float4 h3 = ((const float4*)&g_h[(size_t)__float_as_int(e3.x) * HDIM])[lane];
        acc.x += e0.y * h0.x; acc.y += e0.y * h0.y; acc.z += e0.y * h0.z; acc.w += e0.y * h0.w;
        acc.x += e1.y * h1.x; acc.y += e1.y * h1.y; acc.z += e1.y * h1.z; acc.w += e1.y * h1.w;
        acc.x += e2.y * h2.x; acc.y += e2.y * h2.y; acc.z += e2.y * h2.z; acc.w += e2.y * h2.w;
        acc.x += e3.y * h3.x; acc.y += e3.y * h3.y; acc.z += e3.y * h3.z; acc.w += e3.y * h3.w;
    }
    for (; j < end; j++) {
        float2 e  = g_edge[j];
        float4 hv = ((const float4*)&g_h[(size_t)__float_as_int(e.x) * HDIM])[lane];
        acc.x += e.y * hv.x; acc.y += e.y * hv.y; acc.z += e.y * hv.z; acc.w += e.y * hv.w;
    }

    float di = g_dinv[node];
    float sw = 2.0f * di * di;

    float4 h4  = ((const float4*)&g_h [(size_t)node * HDIM])[lane];
    float4 hs4 = ((const float4*)&g_hs[(size_t)node * HDIM])[lane];
    float4 bc  = ((const float4*)bconv)[lane];
    float4 bs  = ((const float4*)bskip)[lane];

    float4 o;
    o.x = acc.x + sw * h4.x + bc.x + hs4.x + bs.x;
    o.y = acc.y + sw * h4.y + bc.y + hs4.y + bs.y;
    o.z = acc.z + sw * h4.z + bc.z + hs4.z + bs.z;
    o.w = acc.w + sw * h4.w + bc.w + hs4.w + bs.w;

    o.x = (o.x > 0.f) ? o.x : 0.1f * (expf(o.x) - 1.0f);
    o.y = (o.y > 0.f) ? o.y : 0.1f * (expf(o.y) - 1.0f);
    o.z = (o.z > 0.f) ? o.z : 0.1f * (expf(o.z) - 1.0f);
    o.w = (o.w > 0.f) ? o.w : 0.1f * (expf(o.w) - 1.0f);

    ((float4*)&out[(size_t)node * HDIM])[lane] = o;
}

// ---------------------------------------------------------------- launch
extern "C" void kernel_launch(void* const* d_in, const int* in_sizes, int n_in,
                              void* d_out, int out_size) {
    const float* x  = (const float*)d_in[0];
    const void*  ei = d_in[1];
    const float* Wc = (const float*)d_in[2];
    const float* bc = (const float*)d_in[3];
    const float* Ws = (const float*)d_in[4];
    const float* bs = (const float*)d_in[5];
    float* out = (float*)d_out;

    const int n = in_sizes[0] / HDIM;
    const int E = in_sizes[1] / 2;

    k_detect <<<1, 32>>>((const int*)ei);
    k_init   <<<(n + 255) / 256, 256>>>(n);
    k_degree <<<(E + 255) / 256, 256>>>(ei, E, n);
    k_offsets<<<(n + 255) / 256, 256>>>(n);
    k_bucket <<<(E + 255) / 256, 256>>>(ei, E, n);

    k_gemm<<<(n + 31) / 32, 256>>>(x, Wc, Ws, n);

    long long athreads = (long long)n * 32;
    k_agg<<<(unsigned)((athreads + 255) / 256), 256>>>(bc, bs, out, n);
}

// round 6
// speedup vs baseline: 1.5104x; 1.0539x over previous
#include <cuda_runtime.h>

#define NMAX 100000
#define EMAX 1600000
#define HDIM 128

// Scratch (static device globals — no runtime allocation)
__device__ __align__(16) int    g_is64;                        // edge dtype flag
__device__             int      g_total;                       // bucket cursor base
__device__ __align__(16) int    g_cnt [NMAX];                  // incoming-edge count
__device__ __align__(16) int    g_off [NMAX];                  // bucket offsets
__device__ __align__(16) int    g_cur [NMAX];                  // bucket cursors
__device__ __align__(16) float  g_dinv[NMAX];                  // 1/sqrt(deg)
__device__ __align__(16) float2 g_edge[EMAX];                  // {src bits, norm} dst-bucketed
__device__ __align__(16) float  g_h   [(size_t)NMAX * HDIM];   // x @ W_conv
__device__ __align__(16) float  g_hs  [(size_t)NMAX * HDIM];   // x @ W_skip

union F2U { unsigned long long u; float2 f; };

__device__ __forceinline__ unsigned long long fma_f32x2(unsigned long long a,
                                                        unsigned long long b,
                                                        unsigned long long c) {
    unsigned long long d;
    asm("fma.rn.f32x2 %0, %1, %2, %3;" : "=l"(d) : "l"(a), "l"(b), "l"(c));
    return d;
}

__device__ __forceinline__ void decode_edge(const void* __restrict__ ei, int E,
                                            int n, int e, int& src, int& dst) {
    if (g_is64) {
        src = (int)((const long long*)ei)[e];
        dst = (int)((const long long*)ei)[(size_t)E + e];
    } else {
        src = ((const int*)ei)[e];
        dst = ((const int*)ei)[(size_t)E + e];
    }
    src = min(max(src, 0), n - 1);
    dst = min(max(dst, 0), n - 1);
}

// ---------------------------------------------------------------- init (+ dtype detect)
// int64 little-endian indices < 2^32 have all-zero high words.
__global__ void k_init(const int* __restrict__ ei32, int n) {
    int i = blockIdx.x * blockDim.x + threadIdx.x;
    if (i == 0) {
        int ornz = 0;
        for (int k = 0; k < 64; k++) ornz |= ei32[2 * k + 1];
        g_is64 = (ornz == 0) ? 1 : 0;
        g_total = 0;
    }
    if (i < n) g_cnt[i] = 0;
}

// ---------------------------------------------------------------- decode + degree histogram
__global__ void k_degree(const void* __restrict__ ei, int E, int n) {
    int e = blockIdx.x * blockDim.x + threadIdx.x;
    if (e >= E) return;
    int src, dst;
    decode_edge(ei, E, n, e, src, dst);
    atomicAdd(&g_cnt[dst], 1);
}

// ---------------------------------------------------------------- offsets (scan-free) + dinv
// Bucket placement order is irrelevant for a counting sort, so offsets come
// from a per-block scan + one global atomicAdd per block (no grid-wide scan).
__global__ void k_offsets(int n) {
    __shared__ int wsum[8];
    __shared__ int bbase;
    int i    = blockIdx.x * 256 + threadIdx.x;
    int lane = threadIdx.x & 31;
    int wid  = threadIdx.x >> 5;

    int c = (i < n) ? g_cnt[i] : 0;
    int v = c;
#pragma unroll
    for (int o = 1; o < 32; o <<= 1) {
        int t = __shfl_up_sync(0xffffffffu, v, o);
        if (lane >= o) v += t;
    }
    if (lane == 31) wsum[wid] = v;
    __syncthreads();
    if (threadIdx.x == 0) {
        int run = 0;
#pragma unroll
        for (int w = 0; w < 8; w++) { int t = wsum[w]; wsum[w] = run; run += t; }
        bbase = atomicAdd(&g_total, run);
    }
    __syncthreads();
    if (i < n) {
        int excl = bbase + wsum[wid] + v - c;
        g_off[i] = excl;
        g_cur[i] = excl;
        g_dinv[i] = rsqrtf((float)c + 2.0f);   // improved=True: +2 self-loop
    }
}

// ---------------------------------------------------------------- bucket (counting sort by dst)
__global__ void k_bucket(const void* __restrict__ ei, int E, int n) {
    int e = blockIdx.x * blockDim.x + threadIdx.x;
    if (e >= E) return;
    int src, dst;
    decode_edge(ei, E, n, e, src, dst);
    float nrm = g_dinv[src] * g_dinv[dst];
    int pos = atomicAdd(&g_cur[dst], 1);
    g_edge[pos] = make_float2(__int_as_float(src), nrm);
}

// ---------------------------------------------------------------- fused dual GEMM (packed f32x2)
// 32 nodes x 256 cols per block, 256 threads, thread tile 8 nodes x 4 cols.
// x stored DUPLICATED in smem ({x,x} per node) so the inner loop is pure
// FFMA2 + LDS: col-pairs come from the W float4, node-dups from sx2.
__global__ __launch_bounds__(256) void k_gemm(const float* __restrict__ x,
                                              const float* __restrict__ Wc,
                                              const float* __restrict__ Ws, int n) {
    __shared__ __align__(16) float sW [32 * 256];   // K-chunk of [W_conv|W_skip]
    __shared__ __align__(16) float sx2[32 * 64];    // K-chunk of x, duplicated pairs

    const int tid   = threadIdx.x;
    const int node0 = blockIdx.x * 32;
    const int c = tid & 63;    // cols 4c..4c+3
    const int r = tid >> 6;    // nodes r*8..r*8+7

    unsigned long long acc[8][2];
#pragma unroll
    for (int i = 0; i < 8; i++) { acc[i][0] = 0ull; acc[i][1] = 0ull; }

    for (int kc = 0; kc < 4; kc++) {
        // W rows [kc*32, kc*32+32): 32 rows x 64 float4
        for (int f = tid; f < 32 * 64; f += 256) {
            int k    = f >> 6;
            int j4   = f & 63;
            int krow = kc * 32 + k;
            float4 v = (j4 < 32) ? ((const float4*)Wc)[krow * 32 + j4]
                                 : ((const float4*)Ws)[krow * 32 + (j4 - 32)];
            ((float4*)&sW[k * 256])[j4] = v;
        }
        // x chunk: 32 nodes x 32 k, stored k-major with each value duplicated
        {
            int nloc = tid & 31;
            int k4   = tid >> 5;               // 0..7 (float4 along K)
            int node = node0 + nloc;
            float4 v = make_float4(0.f, 0.f, 0.f, 0.f);
            if (node < n) v = ((const float4*)x)[(size_t)node * 32 + kc * 8 + k4];
            ((float2*)&sx2[(k4 * 4 + 0) * 64])[nloc] = make_float2(v.x, v.x);
            ((float2*)&sx2[(k4 * 4 + 1) * 64])[nloc] = make_float2(v.y, v.y);
            ((float2*)&sx2[(k4 * 4 + 2) * 64])[nloc] = make_float2(v.z, v.z);
            ((float2*)&sx2[(k4 * 4 + 3) * 64])[nloc] = make_float2(v.w, v.w);
        }
        __syncthreads();

#pragma unroll 8
        for (int k = 0; k < 32; k++) {
            ulonglong2 wu = *(const ulonglong2*)&sW[k * 256 + c * 4];  // 2 col-pairs
            const ulonglong2* xp = (const ulonglong2*)&sx2[k * 64 + r * 16];
            ulonglong2 x01 = xp[0], x23 = xp[1], x45 = xp[2], x67 = xp[3];
            acc[0][0] = fma_f32x2(x01.x, wu.x, acc[0][0]);
            acc[0][1] = fma_f32x2(x01.x, wu.y, acc[0][1]);
            acc[1][0] = fma_f32x2(x01.y, wu.x, acc[1][0]);
            acc[1][1] = fma_f32x2(x01.y, wu.y, acc[1][1]);
            acc[2][0] = fma_f32x2(x23.x, wu.x, acc[2][0]);
            acc[2][1] = fma_f32x2(x23.x, wu.y, acc[2][1]);
            acc[3][0] = fma_f32x2(x23.y, wu.x, acc[3][0]);
            acc[3][1] = fma_f32x2(x23.y, wu.y, acc[3][1]);
            acc[4][0] = fma_f32x2(x45.x, wu.x, acc[4][0]);
            acc[4][1] = fma_f32x2(x45.x, wu.y, acc[4][1]);
            acc[5][0] = fma_f32x2(x45.y, wu.x, acc[5][0]);
            acc[5][1] = fma_f32x2(x45.y, wu.y, acc[5][1]);
            acc[6][0] = fma_f32x2(x67.x, wu.x, acc[6][0]);
            acc[6][1] = fma_f32x2(x67.x, wu.y, acc[6][1]);
            acc[7][0] = fma_f32x2(x67.y, wu.x, acc[7][0]);
            acc[7][1] = fma_f32x2(x67.y, wu.y, acc[7][1]);
        }
        __syncthreads();
    }

#pragma unroll
    for (int i = 0; i < 8; i++) {
        int node = node0 + r * 8 + i;
        if (node < n) {
            F2U a0, a1;
            a0.u = acc[i][0];
            a1.u = acc[i][1];
            float4 o = make_float4(a0.f.x, a0.f.y, a1.f.x, a1.f.y);
            if (c < 32) ((float4*)&g_h [(size_t)node * HDIM])[c]      = o;
            else        ((float4*)&g_hs[(size_t)node * HDIM])[c - 32] = o;
        }
    }
}

// ---------------------------------------------------------------- fused aggregation + epilogue
// One warp per node, lane l owns features [4l, 4l+4). Unroll-8 for MLP.
__global__ __launch_bounds__(256) void k_agg(const float* __restrict__ bconv,
                                             const float* __restrict__ bskip,
                                             float* __restrict__ out, int n) {
    int node = (blockIdx.x * blockDim.x + threadIdx.x) >> 5;
    int lane = threadIdx.x & 31;
    if (node >= n) return;

    const int beg = g_off[node];
    const int end = beg + g_cnt[node];

    float4 acc = make_float4(0.f, 0.f, 0.f, 0.f);
    int j = beg;
    for (; j + 8 <= end; j += 8) {
        float2 e[8];
        float4 h[8];
#pragma unroll
        for (int u = 0; u < 8; u++) e[u] = g_edge[j + u];
#pragma unroll
        for (int u = 0; u < 8; u++)
            h[u] = ((const float4*)&g_h[(size_t)__float_as_int(e[u].x) * HDIM])[lane];
#pragma unroll
        for (int u = 0; u < 8; u++) {
            acc.x += e[u].y * h[u].x;
            acc.y += e[u].y * h[u].y;
            acc.z += e[u].y * h[u].z;
            acc.w += e[u].y * h[u].w;
        }
    }
    for (; j < end; j++) {
        float2 e  = g_edge[j];
        float4 hv = ((const float4*)&g_h[(size_t)__float_as_int(e.x) * HDIM])[lane];
        acc.x += e.y * hv.x; acc.y += e.y * hv.y; acc.z += e.y * hv.z; acc.w += e.y * hv.w;
    }

    float di = g_dinv[node];
    float sw = 2.0f * di * di;

    float4 h4  = ((const float4*)&g_h [(size_t)node * HDIM])[lane];
    float4 hs4 = ((const float4*)&g_hs[(size_t)node * HDIM])[lane];
    float4 bc  = ((const float4*)bconv)[lane];
    float4 bs  = ((const float4*)bskip)[lane];

    float4 o;
    o.x = acc.x + sw * h4.x + bc.x + hs4.x + bs.x;
    o.y = acc.y + sw * h4.y + bc.y + hs4.y + bs.y;
    o.z = acc.z + sw * h4.z + bc.z + hs4.z + bs.z;
    o.w = acc.w + sw * h4.w + bc.w + hs4.w + bs.w;

    o.x = (o.x > 0.f) ? o.x : 0.1f * (__expf(o.x) - 1.0f);
    o.y = (o.y > 0.f) ? o.y : 0.1f * (__expf(o.y) - 1.0f);
    o.z = (o.z > 0.f) ? o.z : 0.1f * (__expf(o.z) - 1.0f);
    o.w = (o.w > 0.f) ? o.w : 0.1f * (__expf(o.w) - 1.0f);

    ((float4*)&out[(size_t)node * HDIM])[lane] = o;
}

// ---------------------------------------------------------------- launch
// GEMM is independent of the edge pre-chain: fork it onto a second stream
// (event fork/join — graph-capture legal), join before k_agg.
extern "C" void kernel_launch(void* const* d_in, const int* in_sizes, int n_in,
                              void* d_out, int out_size) {
    const float* x  = (const float*)d_in[0];
    const void*  ei = d_in[1];
    const float* Wc = (const float*)d_in[2];
    const float* bc = (const float*)d_in[3];
    const float* Ws = (const float*)d_in[4];
    const float* bs = (const float*)d_in[5];
    float* out = (float*)d_out;

    const int n = in_sizes[0] / HDIM;
    const int E = in_sizes[1] / 2;

    // One-time host resources (created on the correctness call, reused under
    // capture; streams/events are host-side objects, not device allocations).
    static cudaStream_t s2 = []() {
        cudaStream_t s; cudaStreamCreateWithFlags(&s, cudaStreamNonBlocking); return s;
    }();
    static cudaEvent_t ev_fork = []() {
        cudaEvent_t e; cudaEventCreateWithFlags(&e, cudaEventDisableTiming); return e;
    }();
    static cudaEvent_t ev_gemm = []() {
        cudaEvent_t e; cudaEventCreateWithFlags(&e, cudaEventDisableTiming); return e;
    }();

    // Fork: GEMM on s2, concurrent with edge preprocessing on the main stream.
    cudaEventRecord(ev_fork, 0);
    cudaStreamWaitEvent(s2, ev_fork, 0);
    k_gemm<<<(n + 31) / 32, 256, 0, s2>>>(x, Wc, Ws, n);
    cudaEventRecord(ev_gemm, s2);

    k_init   <<<(n + 255) / 256, 256>>>((const int*)ei, n);
    k_degree <<<(E + 255) / 256, 256>>>(ei, E, n);
    k_offsets<<<(n + 255) / 256, 256>>>(n);
    k_bucket <<<(E + 255) / 256, 256>>>(ei, E, n);

    // Join: aggregation needs both the bucketed edges and g_h/g_hs.
    cudaStreamWaitEvent(0, ev_gemm, 0);
    long long athreads = (long long)n * 32;
    k_agg<<<(unsigned)((athreads + 255) / 256), 256>>>(bc, bs, out, n);
}

// round 8
// speedup vs baseline: 1.5410x; 1.0203x over previous
#include <cuda_runtime.h>
#include <cuda_fp16.h>
#include <cstdint>

#define NMAX 100000
#define EMAX 1600000
#define HDIM 128

// Scratch (static device globals — no runtime allocation)
__device__ __align__(16) int    g_is64;                        // edge dtype flag
__device__             int      g_total;                       // bucket cursor base
__device__ __align__(16) int    g_cnt [NMAX];                  // incoming-edge count
__device__ __align__(16) int    g_off [NMAX];                  // bucket offsets
__device__ __align__(16) int    g_cur [NMAX];                  // bucket cursors
__device__ __align__(16) float  g_dinv[NMAX];                  // 1/sqrt(deg)
__device__ __align__(16) float2 g_edge[EMAX];                  // {src bits, norm} dst-bucketed
__device__ __align__(16) float  g_h   [(size_t)NMAX * HDIM];   // x @ W_conv (fp32)
__device__ __align__(16) __half g_h16 [(size_t)NMAX * HDIM];   // x @ W_conv (fp16 gather copy)
__device__ __align__(16) float  g_hs  [(size_t)NMAX * HDIM];   // x @ W_skip

union F2U { unsigned long long u; float2 f; };

__device__ __forceinline__ unsigned long long fma_f32x2(unsigned long long a,
                                                        unsigned long long b,
                                                        unsigned long long c) {
    unsigned long long d;
    asm("fma.rn.f32x2 %0, %1, %2, %3;" : "=l"(d) : "l"(a), "l"(b), "l"(c));
    return d;
}

__device__ __forceinline__ void decode_edge(const void* __restrict__ ei, int E,
                                            int n, int e, int& src, int& dst) {
    if (g_is64) {
        src = (int)((const long long*)ei)[e];
        dst = (int)((const long long*)ei)[(size_t)E + e];
    } else {
        src = ((const int*)ei)[e];
        dst = ((const int*)ei)[(size_t)E + e];
    }
    src = min(max(src, 0), n - 1);
    dst = min(max(dst, 0), n - 1);
}

// ---------------------------------------------------------------- init (+ dtype detect)
// int64 little-endian indices < 2^32 have all-zero high words.
__global__ void k_init(const int* __restrict__ ei32, int n) {
    int i = blockIdx.x * blockDim.x + threadIdx.x;
    if (i == 0) {
        int ornz = 0;
        for (int k = 0; k < 64; k++) ornz |= ei32[2 * k + 1];
        g_is64 = (ornz == 0) ? 1 : 0;
        g_total = 0;
    }
    if (i < n) g_cnt[i] = 0;
}

// ---------------------------------------------------------------- decode + degree histogram
__global__ void k_degree(const void* __restrict__ ei, int E, int n) {
    int e = blockIdx.x * blockDim.x + threadIdx.x;
    if (e >= E) return;
    int src, dst;
    decode_edge(ei, E, n, e, src, dst);
    atomicAdd(&g_cnt[dst], 1);
}

// ---------------------------------------------------------------- offsets (scan-free) + dinv
__global__ void k_offsets(int n) {
    __shared__ int wsum[8];
    __shared__ int bbase;
    int i    = blockIdx.x * 256 + threadIdx.x;
    int lane = threadIdx.x & 31;
    int wid  = threadIdx.x >> 5;

    int c = (i < n) ? g_cnt[i] : 0;
    int v = c;
#pragma unroll
    for (int o = 1; o < 32; o <<= 1) {
        int t = __shfl_up_sync(0xffffffffu, v, o);
        if (lane >= o) v += t;
    }
    if (lane == 31) wsum[wid] = v;
    __syncthreads();
    if (threadIdx.x == 0) {
        int run = 0;
#pragma unroll
        for (int w = 0; w < 8; w++) { int t = wsum[w]; wsum[w] = run; run += t; }
        bbase = atomicAdd(&g_total, run);
    }
    __syncthreads();
    if (i < n) {
        int excl = bbase + wsum[wid] + v - c;
        g_off[i] = excl;
        g_cur[i] = excl;
        g_dinv[i] = rsqrtf((float)c + 2.0f);   // improved=True: +2 self-loop
    }
}

// ---------------------------------------------------------------- bucket (counting sort by dst)
__global__ void k_bucket(const void* __restrict__ ei, int E, int n) {
    int e = blockIdx.x * blockDim.x + threadIdx.x;
    if (e >= E) return;
    int src, dst;
    decode_edge(ei, E, n, e, src, dst);
    float nrm = g_dinv[src] * g_dinv[dst];
    int pos = atomicAdd(&g_cur[dst], 1);
    g_edge[pos] = make_float2(__int_as_float(src), nrm);
}

// ---------------------------------------------------------------- fused dual GEMM (packed f32x2)
// 32 nodes x 256 cols per block, 256 threads, thread tile 8 nodes x 4 cols.
// x stored DUPLICATED in smem ({x,x} per node) so the inner loop is pure
// FFMA2 + LDS. Conv half also emits an fp16 copy for the agg gathers.
__global__ __launch_bounds__(256) void k_gemm(const float* __restrict__ x,
                                              const float* __restrict__ Wc,
                                              const float* __restrict__ Ws, int n) {
    __shared__ __align__(16) float sW [32 * 256];   // K-chunk of [W_conv|W_skip]
    __shared__ __align__(16) float sx2[32 * 64];    // K-chunk of x, duplicated pairs

    const int tid   = threadIdx.x;
    const int node0 = blockIdx.x * 32;
    const int c = tid & 63;    // cols 4c..4c+3
    const int r = tid >> 6;    // nodes r*8..r*8+7

    unsigned long long acc[8][2];
#pragma unroll
    for (int i = 0; i < 8; i++) { acc[i][0] = 0ull; acc[i][1] = 0ull; }

    for (int kc = 0; kc < 4; kc++) {
        for (int f = tid; f < 32 * 64; f += 256) {
            int k    = f >> 6;
            int j4   = f & 63;
            int krow = kc * 32 + k;
            float4 v = (j4 < 32) ? ((const float4*)Wc)[krow * 32 + j4]
                                 : ((const float4*)Ws)[krow * 32 + (j4 - 32)];
            ((float4*)&sW[k * 256])[j4] = v;
        }
        {
            int nloc = tid & 31;
            int k4   = tid >> 5;               // 0..7 (float4 along K)
            int node = node0 + nloc;
            float4 v = make_float4(0.f, 0.f, 0.f, 0.f);
            if (node < n) v = ((const float4*)x)[(size_t)node * 32 + kc * 8 + k4];
            ((float2*)&sx2[(k4 * 4 + 0) * 64])[nloc] = make_float2(v.x, v.x);
            ((float2*)&sx2[(k4 * 4 + 1) * 64])[nloc] = make_float2(v.y, v.y);
            ((float2*)&sx2[(k4 * 4 + 2) * 64])[nloc] = make_float2(v.z, v.z);
            ((float2*)&sx2[(k4 * 4 + 3) * 64])[nloc] = make_float2(v.w, v.w);
        }
        __syncthreads();

#pragma unroll 8
        for (int k = 0; k < 32; k++) {
            ulonglong2 wu = *(const ulonglong2*)&sW[k * 256 + c * 4];
            const ulonglong2* xp = (const ulonglong2*)&sx2[k * 64 + r * 16];
            ulonglong2 x01 = xp[0], x23 = xp[1], x45 = xp[2], x67 = xp[3];
            acc[0][0] = fma_f32x2(x01.x, wu.x, acc[0][0]);
            acc[0][1] = fma_f32x2(x01.x, wu.y, acc[0][1]);
            acc[1][0] = fma_f32x2(x01.y, wu.x, acc[1][0]);
            acc[1][1] = fma_f32x2(x01.y, wu.y, acc[1][1]);
            acc[2][0] = fma_f32x2(x23.x, wu.x, acc[2][0]);
            acc[2][1] = fma_f32x2(x23.x, wu.y, acc[2][1]);
            acc[3][0] = fma_f32x2(x23.y, wu.x, acc[3][0]);
            acc[3][1] = fma_f32x2(x23.y, wu.y, acc[3][1]);
            acc[4][0] = fma_f32x2(x45.x, wu.x, acc[4][0]);
            acc[4][1] = fma_f32x2(x45.x, wu.y, acc[4][1]);
            acc[5][0] = fma_f32x2(x45.y, wu.x, acc[5][0]);
            acc[5][1] = fma_f32x2(x45.y, wu.y, acc[5][1]);
            acc[6][0] = fma_f32x2(x67.x, wu.x, acc[6][0]);
            acc[6][1] = fma_f32x2(x67.x, wu.y, acc[6][1]);
            acc[7][0] = fma_f32x2(x67.y, wu.x, acc[7][0]);
            acc[7][1] = fma_f32x2(x67.y, wu.y, acc[7][1]);
        }
        __syncthreads();
    }

#pragma unroll
    for (int i = 0; i < 8; i++) {
        int node = node0 + r * 8 + i;
        if (node < n) {
            F2U a0, a1;
            a0.u = acc[i][0];
            a1.u = acc[i][1];
            float4 o = make_float4(a0.f.x, a0.f.y, a1.f.x, a1.f.y);
            if (c < 32) {
                ((float4*)&g_h[(size_t)node * HDIM])[c] = o;
                __half2 p0 = __floats2half2_rn(o.x, o.y);
                __half2 p1 = __floats2half2_rn(o.z, o.w);
                uint2 packed;
                packed.x = *(uint32_t*)&p0;
                packed.y = *(uint32_t*)&p1;
                ((uint2*)&g_h16[(size_t)node * HDIM])[c] = packed;
            } else {
                ((float4*)&g_hs[(size_t)node * HDIM])[c - 32] = o;
            }
        }
    }
}

// ---------------------------------------------------------------- fused aggregation + epilogue
// One warp per node, lane l owns features [4l, 4l+4). fp16 gathers (256 B/edge).
__global__ __launch_bounds__(256) void k_agg(const float* __restrict__ bconv,
                                             const float* __restrict__ bskip,
                                             float* __restrict__ out, int n) {
    int node = (blockIdx.x * blockDim.x + threadIdx.x) >> 5;
    int lane = threadIdx.x & 31;
    if (node >= n) return;

    const int beg = g_off[node];
    const int end = beg + g_cnt[node];

    float4 acc = make_float4(0.f, 0.f, 0.f, 0.f);
    int j = beg;
    for (; j + 8 <= end; j += 8) {
        float2 e[8];
        uint2  h[8];
#pragma unroll
        for (int u = 0; u < 8; u++) e[u] = g_edge[j + u];
#pragma unroll
        for (int u = 0; u < 8; u++)
            h[u] = ((const uint2*)&g_h16[(size_t)__float_as_int(e[u].x) * HDIM])[lane];
#pragma unroll
        for (int u = 0; u < 8; u++) {
            float2 f01 = __half22float2(*(__half2*)&h[u].x);
            float2 f23 = __half22float2(*(__half2*)&h[u].y);
            acc.x += e[u].y * f01.x;
            acc.y += e[u].y * f01.y;
            acc.z += e[u].y * f23.x;
            acc.w += e[u].y * f23.y;
        }
    }
    for (; j < end; j++) {
        float2 e  = g_edge[j];
        uint2  hv = ((const uint2*)&g_h16[(size_t)__float_as_int(e.x) * HDIM])[lane];
        float2 f01 = __half22float2(*(__half2*)&hv.x);
        float2 f23 = __half22float2(*(__half2*)&hv.y);
        acc.x += e.y * f01.x;
        acc.y += e.y * f01.y;
        acc.z += e.y * f23.x;
        acc.w += e.y * f23.y;
    }

    float di = g_dinv[node];
    float sw = 2.0f * di * di;

    float4 h4  = ((const float4*)&g_h [(size_t)node * HDIM])[lane];
    float4 hs4 = ((const float4*)&g_hs[(size_t)node * HDIM])[lane];
    float4 bc  = ((const float4*)bconv)[lane];
    float4 bs  = ((const float4*)bskip)[lane];

    float4 o;
    o.x = acc.x + sw * h4.x + bc.x + hs4.x + bs.x;
    o.y = acc.y + sw * h4.y + bc.y + hs4.y + bs.y;
    o.z = acc.z + sw * h4.z + bc.z + hs4.z + bs.z;
    o.w = acc.w + sw * h4.w + bc.w + hs4.w + bs.w;

    o.x = (o.x > 0.f) ? o.x : 0.1f * (__expf(o.x) - 1.0f);
    o.y = (o.y > 0.f) ? o.y : 0.1f * (__expf(o.y) - 1.0f);
    o.z = (o.z > 0.f) ? o.z : 0.1f * (__expf(o.z) - 1.0f);
    o.w = (o.w > 0.f) ? o.w : 0.1f * (__expf(o.w) - 1.0f);

    ((float4*)&out[(size_t)node * HDIM])[lane] = o;
}

// ---------------------------------------------------------------- launch
extern "C" void kernel_launch(void* const* d_in, const int* in_sizes, int n_in,
                              void* d_out, int out_size) {
    const float* x  = (const float*)d_in[0];
    const void*  ei = d_in[1];
    const float* Wc = (const float*)d_in[2];
    const float* bc = (const float*)d_in[3];
    const float* Ws = (const float*)d_in[4];
    const float* bs = (const float*)d_in[5];
    float* out = (float*)d_out;

    const int n = in_sizes[0] / HDIM;
    const int E = in_sizes[1] / 2;

    static cudaStream_t s2 = []() {
        cudaStream_t s; cudaStreamCreateWithFlags(&s, cudaStreamNonBlocking); return s;
    }();
    static cudaEvent_t ev_fork = []() {
        cudaEvent_t e; cudaEventCreateWithFlags(&e, cudaEventDisableTiming); return e;
    }();
    static cudaEvent_t ev_gemm = []() {
        cudaEvent_t e; cudaEventCreateWithFlags(&e, cudaEventDisableTiming); return e;
    }();

    // Fork: GEMM on s2, concurrent with edge preprocessing on the main stream.
    cudaEventRecord(ev_fork, 0);
    cudaStreamWaitEvent(s2, ev_fork, 0);
    k_gemm<<<(n + 31) / 32, 256, 0, s2>>>(x, Wc, Ws, n);
    cudaEventRecord(ev_gemm, s2);

    k_init   <<<(n + 255) / 256, 256>>>((const int*)ei, n);
    k_degree <<<(E + 255) / 256, 256>>>(ei, E, n);
    k_offsets<<<(n + 255) / 256, 256>>>(n);
    k_bucket <<<(E + 255) / 256, 256>>>(ei, E, n);

    // Join: aggregation needs both the bucketed edges and g_h/g_hs.
    cudaStreamWaitEvent(0, ev_gemm, 0);
    long long athreads = (long long)n * 32;
    k_agg<<<(unsigned)((athreads + 255) / 256), 256>>>(bc, bs, out, n);
}

// round 9
// speedup vs baseline: 1.9978x; 1.2964x over previous
#include <cuda_runtime.h>
#include <cuda_fp16.h>
#include <cstdint>

#define NMAX 100000
#define EMAX 1600000
#define HDIM 128

// Scratch (static device globals — no runtime allocation)
__device__ __align__(16) int    g_is64;                        // edge dtype flag
__device__             int      g_total;                       // bucket cursor base
__device__ __align__(16) int    g_cnt [NMAX];                  // incoming-edge count
__device__ __align__(16) int    g_off [NMAX];                  // bucket offsets
__device__ __align__(16) int    g_cur [NMAX];                  // bucket cursors
__device__ __align__(16) float  g_dinv[NMAX];                  // 1/sqrt(deg)
__device__ __align__(16) float2 g_edge[EMAX];                  // {src bits, norm} dst-bucketed
__device__ __align__(16) float  g_h   [(size_t)NMAX * HDIM];   // x @ W_conv (fp32)
__device__ __align__(16) __half g_h16 [(size_t)NMAX * HDIM];   // x @ W_conv (fp16 gather copy)
__device__ __align__(16) float  g_hs  [(size_t)NMAX * HDIM];   // x @ W_skip

__device__ __forceinline__ void decode_edge(const void* __restrict__ ei, int E,
                                            int n, int e, int& src, int& dst) {
    if (g_is64) {
        src = (int)((const long long*)ei)[e];
        dst = (int)((const long long*)ei)[(size_t)E + e];
    } else {
        src = ((const int*)ei)[e];
        dst = ((const int*)ei)[(size_t)E + e];
    }
    src = min(max(src, 0), n - 1);
    dst = min(max(dst, 0), n - 1);
}

// ---------------------------------------------------------------- init (+ dtype detect)
__global__ void k_init(const int* __restrict__ ei32, int n) {
    int i = blockIdx.x * blockDim.x + threadIdx.x;
    if (i == 0) {
        int ornz = 0;
        for (int k = 0; k < 64; k++) ornz |= ei32[2 * k + 1];
        g_is64 = (ornz == 0) ? 1 : 0;
        g_total = 0;
    }
    if (i < n) g_cnt[i] = 0;
}

// ---------------------------------------------------------------- degree histogram
__global__ void k_degree(const void* __restrict__ ei, int E, int n) {
    int e = blockIdx.x * blockDim.x + threadIdx.x;
    if (e >= E) return;
    int src, dst;
    decode_edge(ei, E, n, e, src, dst);
    atomicAdd(&g_cnt[dst], 1);
}

// ---------------------------------------------------------------- offsets (scan-free) + dinv
__global__ void k_offsets(int n) {
    __shared__ int wsum[8];
    __shared__ int bbase;
    int i    = blockIdx.x * 256 + threadIdx.x;
    int lane = threadIdx.x & 31;
    int wid  = threadIdx.x >> 5;

    int c = (i < n) ? g_cnt[i] : 0;
    int v = c;
#pragma unroll
    for (int o = 1; o < 32; o <<= 1) {
        int t = __shfl_up_sync(0xffffffffu, v, o);
        if (lane >= o) v += t;
    }
    if (lane == 31) wsum[wid] = v;
    __syncthreads();
    if (threadIdx.x == 0) {
        int run = 0;
#pragma unroll
        for (int w = 0; w < 8; w++) { int t = wsum[w]; wsum[w] = run; run += t; }
        bbase = atomicAdd(&g_total, run);
    }
    __syncthreads();
    if (i < n) {
        int excl = bbase + wsum[wid] + v - c;
        g_off[i] = excl;
        g_cur[i] = excl;
        g_dinv[i] = rsqrtf((float)c + 2.0f);   // improved=True: +2 self-loop
    }
}

// ---------------------------------------------------------------- bucket (counting sort by dst)
__global__ void k_bucket(const void* __restrict__ ei, int E, int n) {
    int e = blockIdx.x * blockDim.x + threadIdx.x;
    if (e >= E) return;
    int src, dst;
    decode_edge(ei, E, n, e, src, dst);
    float nrm = g_dinv[src] * g_dinv[dst];
    int pos = atomicAdd(&g_cur[dst], 1);
    g_edge[pos] = make_float2(__int_as_float(src), nrm);
}

// ---------------------------------------------------------------- HMMA dual GEMM
// mma.sync m16n8k16 fp16 (base ISA). Split precision:
//   D = x_hi·W_hi + x_lo·W_hi + x_hi·W_lo   (lo·lo term ~2^-22, dropped)
// CTA: 128 nodes x 256 cols (conv|skip), 512 threads = 16 warps,
// warp tile 32x64. K chunked by 32 in smem; row stride 40 halves
// (conflict-free for the fragment LDS pattern).
#define SA_STR 40
#define SB_STR 40
#define SA_HALVES (128 * SA_STR)            // per hi/lo tile
#define SB_HALVES (256 * SB_STR)
#define SMEM_MMA ((2 * SA_HALVES + 2 * SB_HALVES) * 2)   // 61440 bytes

__device__ __forceinline__ void mma16816(float* d, const uint32_t* a,
                                         uint32_t b0, uint32_t b1) {
    asm volatile(
        "mma.sync.aligned.m16n8k16.row.col.f32.f16.f16.f32 "
        "{%0,%1,%2,%3}, {%4,%5,%6,%7}, {%8,%9}, {%0,%1,%2,%3};"
        : "+f"(d[0]), "+f"(d[1]), "+f"(d[2]), "+f"(d[3])
        : "r"(a[0]), "r"(a[1]), "r"(a[2]), "r"(a[3]), "r"(b0), "r"(b1));
}

__device__ __forceinline__ uint32_t pack_half2(float a, float b) {
    __half2 h = __floats2half2_rn(a, b);
    return *(uint32_t*)&h;
}

__global__ __launch_bounds__(512) void k_gemm_mma(const float* __restrict__ x,
                                                  const float* __restrict__ Wc,
                                                  const float* __restrict__ Ws,
                                                  int n) {
    extern __shared__ __align__(16) __half smem[];
    __half* sAhi = smem;
    __half* sAlo = sAhi + SA_HALVES;
    __half* sBhi = sAlo + SA_HALVES;
    __half* sBlo = sBhi + SB_HALVES;

    const int tid  = threadIdx.x;
    const int wid  = tid >> 5;
    const int lane = tid & 31;
    const int g    = lane >> 2;     // group id (0..7)
    const int tg   = lane & 3;      // thread in group
    const int mw   = (wid & 3) * 32;    // warp M offset (rows)
    const int nw   = (wid >> 2) * 64;   // warp N offset (cols of 256)
    const int node0 = blockIdx.x * 128;

    float d[2][8][4];
#pragma unroll
    for (int mi = 0; mi < 2; mi++)
#pragma unroll
        for (int ni = 0; ni < 8; ni++)
#pragma unroll
            for (int q = 0; q < 4; q++) d[mi][ni][q] = 0.f;

    for (int kc = 0; kc < 4; kc++) {
        // ---- load + split x chunk: 128 rows x 32 k (1024 float4, 2/thread)
#pragma unroll
        for (int i = 0; i < 2; i++) {
            int f4  = i * 512 + tid;
            int row = f4 >> 3;
            int k4  = f4 & 7;
            int node = node0 + row;
            float4 v = make_float4(0.f, 0.f, 0.f, 0.f);
            if (node < n) v = ((const float4*)x)[(size_t)node * 32 + kc * 8 + k4];
            float hx = __half2float(__float2half_rn(v.x));
            float hy = __half2float(__float2half_rn(v.y));
            float hz = __half2float(__float2half_rn(v.z));
            float hw = __half2float(__float2half_rn(v.w));
            int base = row * SA_STR + k4 * 4;
            *(uint32_t*)&sAhi[base]     = pack_half2(hx, hy);
            *(uint32_t*)&sAhi[base + 2] = pack_half2(hz, hw);
            *(uint32_t*)&sAlo[base]     = pack_half2(v.x - hx, v.y - hy);
            *(uint32_t*)&sAlo[base + 2] = pack_half2(v.z - hz, v.w - hw);
        }
        // ---- load + split W chunk: 32 k x 256 cols (8192 elems, 16/thread)
#pragma unroll
        for (int i = 0; i < 16; i++) {
            int f    = i * 512 + tid;
            int k    = f >> 8;
            int ncol = f & 255;
            int krow = kc * 32 + k;
            float v = (ncol < 128) ? Wc[krow * 128 + ncol]
                                   : Ws[krow * 128 + (ncol - 128)];
            __half hi = __float2half_rn(v);
            sBhi[ncol * SB_STR + k] = hi;
            sBlo[ncol * SB_STR + k] = __float2half_rn(v - __half2float(hi));
        }
        __syncthreads();

        // ---- 3 split passes x 2 k16 steps
#pragma unroll
        for (int p = 0; p < 3; p++) {
            const __half* A = (p == 1) ? sAlo : sAhi;
            const __half* B = (p == 2) ? sBlo : sBhi;
#pragma unroll
            for (int kk = 0; kk < 32; kk += 16) {
                uint32_t a[2][4];
#pragma unroll
                for (int mi = 0; mi < 2; mi++) {
                    int r0 = (mw + mi * 16 + g) * SA_STR + kk + tg * 2;
                    int r1 = r0 + 8 * SA_STR;
                    a[mi][0] = *(const uint32_t*)(A + r0);
                    a[mi][1] = *(const uint32_t*)(A + r1);
                    a[mi][2] = *(const uint32_t*)(A + r0 + 8);
                    a[mi][3] = *(const uint32_t*)(A + r1 + 8);
                }
#pragma unroll
                for (int ni = 0; ni < 8; ni++) {
                    int nb = (nw + ni * 8 + g) * SB_STR + kk + tg * 2;
                    uint32_t b0 = *(const uint32_t*)(B + nb);
                    uint32_t b1 = *(const uint32_t*)(B + nb + 8);
                    mma16816(d[0][ni], a[0], b0, b1);
                    mma16816(d[1][ni], a[1], b0, b1);
                }
            }
        }
        __syncthreads();
    }

    // ---- epilogue: D element (mi, ni, q): row = mw + mi*16 + g + (q>>1)*8,
    //      col = nw + ni*8 + tg*2 + (q&1)
#pragma unroll
    for (int mi = 0; mi < 2; mi++) {
#pragma unroll
        for (int hr = 0; hr < 2; hr++) {
            int node = node0 + mw + mi * 16 + g + hr * 8;
            if (node >= n) continue;
#pragma unroll
            for (int ni = 0; ni < 8; ni++) {
                int col = nw + ni * 8 + tg * 2;
                float v0 = d[mi][ni][hr * 2 + 0];
                float v1 = d[mi][ni][hr * 2 + 1];
                if (col < 128) {
                    *(float2*)&g_h[(size_t)node * HDIM + col] = make_float2(v0, v1);
                    *(uint32_t*)&g_h16[(size_t)node * HDIM + col] = pack_half2(v0, v1);
                } else {
                    *(float2*)&g_hs[(size_t)node * HDIM + (col - 128)] =
                        make_float2(v0, v1);
                }
            }
        }
    }
}

// ---------------------------------------------------------------- fused aggregation + epilogue
// One warp per node, lane l owns features [4l, 4l+4). fp16 gathers (256 B/edge).
__global__ __launch_bounds__(256) void k_agg(const float* __restrict__ bconv,
                                             const float* __restrict__ bskip,
                                             float* __restrict__ out, int n) {
    int node = (blockIdx.x * blockDim.x + threadIdx.x) >> 5;
    int lane = threadIdx.x & 31;
    if (node >= n) return;

    const int beg = g_off[node];
    const int end = beg + g_cnt[node];

    float4 acc = make_float4(0.f, 0.f, 0.f, 0.f);
    int j = beg;
    for (; j + 8 <= end; j += 8) {
        float2 e[8];
        uint2  h[8];
#pragma unroll
        for (int u = 0; u < 8; u++) e[u] = g_edge[j + u];
#pragma unroll
        for (int u = 0; u < 8; u++)
            h[u] = ((const uint2*)&g_h16[(size_t)__float_as_int(e[u].x) * HDIM])[lane];
#pragma unroll
        for (int u = 0; u < 8; u++) {
            float2 f01 = __half22float2(*(__half2*)&h[u].x);
            float2 f23 = __half22float2(*(__half2*)&h[u].y);
            acc.x += e[u].y * f01.x;
            acc.y += e[u].y * f01.y;
            acc.z += e[u].y * f23.x;
            acc.w += e[u].y * f23.y;
        }
    }
    for (; j < end; j++) {
        float2 e  = g_edge[j];
        uint2  hv = ((const uint2*)&g_h16[(size_t)__float_as_int(e.x) * HDIM])[lane];
        float2 f01 = __half22float2(*(__half2*)&hv.x);
        float2 f23 = __half22float2(*(__half2*)&hv.y);
        acc.x += e.y * f01.x;
        acc.y += e.y * f01.y;
        acc.z += e.y * f23.x;
        acc.w += e.y * f23.y;
    }

    float di = g_dinv[node];
    float sw = 2.0f * di * di;

    float4 h4  = ((const float4*)&g_h [(size_t)node * HDIM])[lane];
    float4 hs4 = ((const float4*)&g_hs[(size_t)node * HDIM])[lane];
    float4 bc  = ((const float4*)bconv)[lane];
    float4 bs  = ((const float4*)bskip)[lane];

    float4 o;
    o.x = acc.x + sw * h4.x + bc.x + hs4.x + bs.x;
    o.y = acc.y + sw * h4.y + bc.y + hs4.y + bs.y;
    o.z = acc.z + sw * h4.z + bc.z + hs4.z + bs.z;
    o.w = acc.w + sw * h4.w + bc.w + hs4.w + bs.w;

    o.x = (o.x > 0.f) ? o.x : 0.1f * (__expf(o.x) - 1.0f);
    o.y = (o.y > 0.f) ? o.y : 0.1f * (__expf(o.y) - 1.0f);
    o.z = (o.z > 0.f) ? o.z : 0.1f * (__expf(o.z) - 1.0f);
    o.w = (o.w > 0.f) ? o.w : 0.1f * (__expf(o.w) - 1.0f);

    ((float4*)&out[(size_t)node * HDIM])[lane] = o;
}

// ---------------------------------------------------------------- launch
extern "C" void kernel_launch(void* const* d_in, const int* in_sizes, int n_in,
                              void* d_out, int out_size) {
    const float* x  = (const float*)d_in[0];
    const void*  ei = d_in[1];
    const float* Wc = (const float*)d_in[2];
    const float* bc = (const float*)d_in[3];
    const float* Ws = (const float*)d_in[4];
    const float* bs = (const float*)d_in[5];
    float* out = (float*)d_out;

    const int n = in_sizes[0] / HDIM;
    const int E = in_sizes[1] / 2;

    static cudaStream_t s2 = []() {
        cudaStream_t s; cudaStreamCreateWithFlags(&s, cudaStreamNonBlocking); return s;
    }();
    static cudaEvent_t ev_fork = []() {
        cudaEvent_t e; cudaEventCreateWithFlags(&e, cudaEventDisableTiming); return e;
    }();
    static cudaEvent_t ev_gemm = []() {
        cudaEvent_t e; cudaEventCreateWithFlags(&e, cudaEventDisableTiming); return e;
    }();
    static bool attr_done = []() {
        cudaFuncSetAttribute(k_gemm_mma,
                             cudaFuncAttributeMaxDynamicSharedMemorySize, SMEM_MMA);
        return true;
    }();
    (void)attr_done;

    // Fork: GEMM on s2, concurrent with edge preprocessing on the main stream.
    cudaEventRecord(ev_fork, 0);
    cudaStreamWaitEvent(s2, ev_fork, 0);
    k_gemm_mma<<<(n + 127) / 128, 512, SMEM_MMA, s2>>>(x, Wc, Ws, n);
    cudaEventRecord(ev_gemm, s2);

    k_init   <<<(n + 255) / 256, 256>>>((const int*)ei, n);
    k_degree <<<(E + 255) / 256, 256>>>(ei, E, n);
    k_offsets<<<(n + 255) / 256, 256>>>(n);
    k_bucket <<<(E + 255) / 256, 256>>>(ei, E, n);

    // Join: aggregation needs both the bucketed edges and g_h/g_hs.
    cudaStreamWaitEvent(0, ev_gemm, 0);
    long long athreads = (long long)n * 32;
    k_agg<<<(unsigned)((athreads + 255) / 256), 256>>>(bc, bs, out, n);
}